// round 1
// baseline (speedup 1.0000x reference)
#include <cuda_runtime.h>

#define B_ 4096
#define S_ 200
#define E_ 128
#define H_ 64
#define G_ 32

// SMEM layout (float offsets)
#define KS_O   0        // keys      200*128 = 25600
#define W1_O   25600    // W1_bot    128*64  = 8192
#define W2_O   33792    // W2        64*32   = 2048
#define QW_O   35840    // q@W1_top + b1     = 64
#define W3_O   35904    // W3                = 32
#define B2_O   35936    // b2                = 32
#define H1_O   35968    // h1 chunk  128*64  = 8192
#define H2_O   44160    // h2 chunk  128*32  = 4096
#define SC_O   48256    // scores/weights    = 200
#define AP_O   48456    // attend partials   = 512
#define RD_O   48968    // reductions        = 64
#define SM_FLOATS 49032
#define SM_BYTES (SM_FLOATS * 4)

// Packed f32x2 FMA with broadcast multiplier: d = {a,a}*b + c
static __device__ __forceinline__ float2 ffma2b(float a, float2 b, float2 c) {
    float2 d;
    asm("{\n\t"
        ".reg .b64 ra, rb, rc, rd;\n\t"
        "mov.b64 ra, {%2, %2};\n\t"
        "mov.b64 rb, {%3, %4};\n\t"
        "mov.b64 rc, {%5, %6};\n\t"
        "fma.rn.f32x2 rd, ra, rb, rc;\n\t"
        "mov.b64 {%0, %1}, rd;\n\t"
        "}"
        : "=f"(d.x), "=f"(d.y)
        : "f"(a), "f"(b.x), "f"(b.y), "f"(c.x), "f"(c.y));
    return d;
}

__global__ __launch_bounds__(512, 1)
void attn_mlp_kernel(const float* __restrict__ query,
                     const float* __restrict__ keys,
                     const int*   __restrict__ mask,
                     const float* __restrict__ W1,
                     const float* __restrict__ b1,
                     const float* __restrict__ W2,
                     const float* __restrict__ b2,
                     const float* __restrict__ W3,
                     const float* __restrict__ b3,
                     float* __restrict__ out)
{
    extern __shared__ float sm[];
    const int b    = blockIdx.x;
    const int t    = threadIdx.x;
    const int warp = t >> 5;
    const int lane = t & 31;

    // ---------------- Phase 1: stage keys + weights into SMEM ----------------
    {
        const float4* gk = reinterpret_cast<const float4*>(keys + (size_t)b * (S_ * E_));
        float4* sk = reinterpret_cast<float4*>(sm + KS_O);
        #pragma unroll 4
        for (int i = t; i < (S_ * E_) / 4; i += 512) sk[i] = gk[i];

        const float4* gw1 = reinterpret_cast<const float4*>(W1 + E_ * H_); // bottom half (keys part)
        float4* sw1 = reinterpret_cast<float4*>(sm + W1_O);
        for (int i = t; i < (E_ * H_) / 4; i += 512) sw1[i] = gw1[i];

        const float4* gw2 = reinterpret_cast<const float4*>(W2);
        float4* sw2 = reinterpret_cast<float4*>(sm + W2_O);
        for (int i = t; i < (H_ * G_) / 4; i += 512) sw2[i] = gw2[i];

        if (t < H_) {   // qW1 = b1 + q @ W1_top  (per-b, once)
            float s = b1[t];
            const float* q = query + (size_t)b * E_;
            #pragma unroll 4
            for (int e = 0; e < E_; ++e) s = fmaf(q[e], W1[e * H_ + t], s);
            sm[QW_O + t] = s;
        }
        if (t >= 64 && t < 96)  sm[W3_O + (t - 64)] = W3[t - 64];
        if (t >= 96 && t < 128) sm[B2_O + (t - 96)] = b2[t - 96];
    }
    __syncthreads();

    const float b3v = b3[0];

    // ---------------- Phase 2: fused MLP -> scores, warp-local -------------
    // Each warp owns 8 consecutive s rows per chunk; 2 chunks cover S=200.
    for (int chunk = 0; chunk < 2; ++chunk) {
        const int s0 = chunk * 128 + warp * 8;   // always full groups of 8 (200 = 25*8)
        const int ls = warp * 8;                 // warp-private rows in h1/h2 buffers

        if (s0 < S_) {
            // ---- Layer 1: h1[s][64] = relu(qW1 + keys[s] @ W1_bot) ----
            const float2 qw = *reinterpret_cast<const float2*>(sm + QW_O + 2 * lane);
            float2 acc[8];
            #pragma unroll
            for (int i = 0; i < 8; ++i) acc[i] = qw;

            const float2* w1p = reinterpret_cast<const float2*>(sm + W1_O);
            #pragma unroll 2
            for (int e = 0; e < E_; e += 4) {
                const float2 wa = w1p[(e + 0) * 32 + lane];
                const float2 wb = w1p[(e + 1) * 32 + lane];
                const float2 wc = w1p[(e + 2) * 32 + lane];
                const float2 wd = w1p[(e + 3) * 32 + lane];
                #pragma unroll
                for (int i = 0; i < 8; ++i) {
                    const float4 k4 = *reinterpret_cast<const float4*>(sm + KS_O + (s0 + i) * E_ + e);
                    acc[i] = ffma2b(k4.x, wa, acc[i]);
                    acc[i] = ffma2b(k4.y, wb, acc[i]);
                    acc[i] = ffma2b(k4.z, wc, acc[i]);
                    acc[i] = ffma2b(k4.w, wd, acc[i]);
                }
            }
            float2* h1 = reinterpret_cast<float2*>(sm + H1_O);
            #pragma unroll
            for (int i = 0; i < 8; ++i) {
                float2 r; r.x = fmaxf(acc[i].x, 0.f); r.y = fmaxf(acc[i].y, 0.f);
                h1[(ls + i) * 32 + lane] = r;
            }
        }
        __syncwarp();

        if (s0 < S_) {
            // ---- Layer 2: h2[s][32] = relu(h1[s] @ W2 + b2) ----
            const int gp = lane & 15;       // output pair index (16 pairs = 32 outputs)
            const int sset = lane >> 4;     // 0/1: which s parity this lane covers
            const float2 bp = *reinterpret_cast<const float2*>(sm + B2_O + 2 * gp);
            float2 acc2[4];
            #pragma unroll
            for (int i = 0; i < 4; ++i) acc2[i] = bp;

            const float2* w2p = reinterpret_cast<const float2*>(sm + W2_O);
            #pragma unroll 4
            for (int h = 0; h < H_; ++h) {
                const float2 wp = w2p[h * 16 + gp];
                #pragma unroll
                for (int i = 0; i < 4; ++i) {
                    const float hv = sm[H1_O + (ls + sset + 2 * i) * H_ + h];
                    acc2[i] = ffma2b(hv, wp, acc2[i]);
                }
            }
            float2* h2 = reinterpret_cast<float2*>(sm + H2_O);
            #pragma unroll
            for (int i = 0; i < 4; ++i) {
                float2 r; r.x = fmaxf(acc2[i].x, 0.f); r.y = fmaxf(acc2[i].y, 0.f);
                h2[(ls + sset + 2 * i) * 16 + gp] = r;
            }
        }
        __syncwarp();

        if (s0 < S_) {
            // ---- Layer 3: score[s] = h2[s] @ W3 + b3, then mask ----
            const int i3 = lane >> 2;   // s row within warp's 8
            const int part = lane & 3;  // quarter of the 32-dim dot
            float ssum = 0.f;
            #pragma unroll
            for (int g = part * 8; g < part * 8 + 8; ++g)
                ssum = fmaf(sm[H2_O + (ls + i3) * G_ + g], sm[W3_O + g], ssum);
            ssum += __shfl_xor_sync(0xffffffffu, ssum, 1);
            ssum += __shfl_xor_sync(0xffffffffu, ssum, 2);
            if (part == 0) {
                const int s = s0 + i3;
                float sc = ssum + b3v;
                if (mask[(size_t)b * S_ + s] == 0) sc = -1e9f;
                sm[SC_O + s] = sc;
            }
        }
        __syncwarp();
    }
    __syncthreads();

    // ---------------- Phase 3: masked softmax over S ----------------
    float m = -3e38f;
    for (int s = t; s < S_; s += 512) m = fmaxf(m, sm[SC_O + s]);
    #pragma unroll
    for (int o = 16; o; o >>= 1) m = fmaxf(m, __shfl_xor_sync(0xffffffffu, m, o));
    if (lane == 0) sm[RD_O + warp] = m;
    __syncthreads();
    if (warp == 0) {
        float v = (lane < 16) ? sm[RD_O + lane] : -3e38f;
        #pragma unroll
        for (int o = 16; o; o >>= 1) v = fmaxf(v, __shfl_xor_sync(0xffffffffu, v, o));
        if (lane == 0) sm[RD_O + 32] = v;
    }
    __syncthreads();
    const float bm = sm[RD_O + 32];

    float ps = 0.f;
    for (int s = t; s < S_; s += 512) {
        const float ex = expf(sm[SC_O + s] - bm);
        sm[SC_O + s] = ex;
        ps += ex;
    }
    #pragma unroll
    for (int o = 16; o; o >>= 1) ps += __shfl_xor_sync(0xffffffffu, ps, o);
    if (lane == 0) sm[RD_O + warp] = ps;
    __syncthreads();
    if (warp == 0) {
        float v = (lane < 16) ? sm[RD_O + lane] : 0.f;
        #pragma unroll
        for (int o = 16; o; o >>= 1) v += __shfl_xor_sync(0xffffffffu, v, o);
        if (lane == 0) sm[RD_O + 33] = v;
    }
    __syncthreads();
    const float inv = 1.0f / sm[RD_O + 33];

    float* out_w = out + (size_t)B_ * E_;   // weights after attended
    for (int s = t; s < S_; s += 512) {
        const float w = sm[SC_O + s] * inv;
        sm[SC_O + s] = w;
        out_w[(size_t)b * S_ + s] = w;
    }
    __syncthreads();

    // ---------------- Phase 4: attended[e] = sum_s w[s]*keys[s][e] ----------
    {
        const int e  = t & 127;
        const int p4 = t >> 7;              // 4 partitions x 50 s each
        float a = 0.f;
        const int sbeg = p4 * 50;
        #pragma unroll 2
        for (int s = sbeg; s < sbeg + 50; ++s)
            a = fmaf(sm[SC_O + s], sm[KS_O + s * E_ + e], a);
        sm[AP_O + p4 * E_ + e] = a;
    }
    __syncthreads();
    if (t < E_) {
        out[(size_t)b * E_ + t] =
            sm[AP_O + t] + sm[AP_O + 128 + t] + sm[AP_O + 256 + t] + sm[AP_O + 384 + t];
    }
}

extern "C" void kernel_launch(void* const* d_in, const int* in_sizes, int n_in,
                              void* d_out, int out_size) {
    const float* query = (const float*)d_in[0];
    const float* keys  = (const float*)d_in[1];
    const int*   mask  = (const int*)d_in[2];
    const float* W1    = (const float*)d_in[3];
    const float* b1    = (const float*)d_in[4];
    const float* W2    = (const float*)d_in[5];
    const float* b2    = (const float*)d_in[6];
    const float* W3    = (const float*)d_in[7];
    const float* b3    = (const float*)d_in[8];
    float* out = (float*)d_out;

    cudaFuncSetAttribute(attn_mlp_kernel,
                         cudaFuncAttributeMaxDynamicSharedMemorySize, SM_BYTES);
    attn_mlp_kernel<<<B_, 512, SM_BYTES>>>(query, keys, mask, W1, b1, W2, b2, W3, b3, out);
}

// round 4
// speedup vs baseline: 1.4914x; 1.4914x over previous
#include <cuda_runtime.h>
#include <cstdint>

#define B_ 4096
#define S_ 200
#define E_ 128
#define H_ 64
#define G_ 32

// ---- padded row strides (bytes); stride % 128 == 16 -> conflict-free ldmatrix
#define RS_K  272   // keys: 128 bf16 (256B) + 16 pad
#define RS_H1 144   // h1:   64 bf16 (128B) + 16 pad
#define RS_W1 272   // W1^T: 128 bf16 + pad
#define RS_W2 144   // W2^T: 64 bf16 + pad

// ---- SMEM byte offsets --------------------------------------------------
#define KHI_O   0        // 208*272 = 56576
#define KLO_O   56576
#define H1HI_O  113152   // 208*144 = 29952
#define H1LO_O  143104
#define W1TH_O  173056   // 64*272 = 17408
#define W1TL_O  190464
#define W2TH_O  207872   // 32*144 = 4608
#define W2TL_O  212480
#define H2_O    173056   // alias W1T region AFTER the post-layer-1 __syncthreads()
#define AP_O    H1HI_O   // alias h1 after layer 2
#define QW_O    217088   // 64 f
#define SC_O    217344   // 200 f
#define RED_O   218144   // 34 f
#define W3S_O   218288   // 32 f
#define B2S_O   218416   // 32 f
#define SMEM_BYTES 218560

// ---------------- helpers ----------------
static __device__ __forceinline__ uint32_t cvta_smem(const void* p) {
    uint32_t a;
    asm("{ .reg .u64 t; cvta.to.shared.u64 t, %1; cvt.u32.u64 %0, t; }" : "=r"(a) : "l"(p));
    return a;
}
// pack two floats to bf16x2: first arg -> low 16, second -> high 16
static __device__ __forceinline__ uint32_t pk(float lo, float hi) {
    uint32_t r;
    asm("cvt.rn.bf16x2.f32 %0, %1, %2;" : "=r"(r) : "f"(hi), "f"(lo));
    return r;
}
static __device__ __forceinline__ float blo(uint32_t u) { return __uint_as_float(u << 16); }
static __device__ __forceinline__ float bhi(uint32_t u) { return __uint_as_float(u & 0xffff0000u); }

static __device__ __forceinline__ void ldsm4(uint32_t& r0, uint32_t& r1, uint32_t& r2, uint32_t& r3,
                                             uint32_t addr) {
    asm volatile("ldmatrix.sync.aligned.m8n8.x4.shared.b16 {%0,%1,%2,%3}, [%4];"
                 : "=r"(r0), "=r"(r1), "=r"(r2), "=r"(r3) : "r"(addr));
}
static __device__ __forceinline__ uint32_t lds32(uint32_t addr) {
    uint32_t v;
    asm volatile("ld.shared.u32 %0, [%1];" : "=r"(v) : "r"(addr));
    return v;
}
static __device__ __forceinline__ void mma_bf16(float* c, const uint32_t* a, uint32_t b0, uint32_t b1) {
    asm volatile("mma.sync.aligned.m16n8k16.row.col.f32.bf16.bf16.f32 "
                 "{%0,%1,%2,%3}, {%4,%5,%6,%7}, {%8,%9}, {%0,%1,%2,%3};"
                 : "+f"(c[0]), "+f"(c[1]), "+f"(c[2]), "+f"(c[3])
                 : "r"(a[0]), "r"(a[1]), "r"(a[2]), "r"(a[3]), "r"(b0), "r"(b1));
}

__global__ __launch_bounds__(512, 1)
void attn_hmma_kernel(const float* __restrict__ query,
                      const float* __restrict__ keys,
                      const int*   __restrict__ mask,
                      const float* __restrict__ W1,
                      const float* __restrict__ b1,
                      const float* __restrict__ W2,
                      const float* __restrict__ b2,
                      const float* __restrict__ W3,
                      const float* __restrict__ b3,
                      float* __restrict__ out)
{
    extern __shared__ char smb[];
    const uint32_t sb = cvta_smem(smb);
    const int b    = blockIdx.x;
    const int t    = threadIdx.x;
    const int warp = t >> 5;
    const int lane = t & 31;

    // ================= Fill phase =================
    {
        // keys -> hi/lo bf16 tiles, rows s, stride RS_K
        const float4* gk = reinterpret_cast<const float4*>(keys + (size_t)b * (S_ * E_));
        #pragma unroll 2
        for (int i = t; i < 6400; i += 512) {
            const int s  = i >> 5;
            const int e0 = (i & 31) * 4;
            const float4 v = gk[i];
            const uint32_t h01 = pk(v.x, v.y), h23 = pk(v.z, v.w);
            const uint32_t l01 = pk(v.x - blo(h01), v.y - bhi(h01));
            const uint32_t l23 = pk(v.z - blo(h23), v.w - bhi(h23));
            const int off = s * RS_K + e0 * 2;
            *(uint64_t*)(smb + KHI_O + off) = (uint64_t)h01 | ((uint64_t)h23 << 32);
            *(uint64_t*)(smb + KLO_O + off) = (uint64_t)l01 | ((uint64_t)l23 << 32);
        }
        // qw = b1 + q @ W1_top (rows 0..127 of W1)
        if (t < 64) {
            const float* q = query + (size_t)b * E_;
            float s1 = b1[t], s2 = 0.f;
            #pragma unroll 4
            for (int e = 0; e < E_; e += 2) {
                s1 = fmaf(q[e],     W1[e * H_ + t],       s1);
                s2 = fmaf(q[e + 1], W1[(e + 1) * H_ + t], s2);
            }
            ((float*)(smb + QW_O))[t] = s1 + s2;
        }
        // W1_bot (rows 128..255) -> W1^T [n][k] hi/lo bf16
        for (int p = t; p < 4096; p += 512) {
            const int n  = p & 63;
            const int kp = p >> 6;
            const float a = W1[(128 + 2 * kp) * H_ + n];
            const float c = W1[(129 + 2 * kp) * H_ + n];
            const uint32_t hu = pk(a, c);
            const uint32_t lu = pk(a - blo(hu), c - bhi(hu));
            *(uint32_t*)(smb + W1TH_O + n * RS_W1 + kp * 4) = hu;
            *(uint32_t*)(smb + W1TL_O + n * RS_W1 + kp * 4) = lu;
        }
        // W2 -> W2^T [g][h] hi/lo bf16
        for (int p = t; p < 1024; p += 512) {
            const int g  = p & 31;
            const int hp = p >> 5;
            const float a = W2[(2 * hp) * G_ + g];
            const float c = W2[(2 * hp + 1) * G_ + g];
            const uint32_t hu = pk(a, c);
            const uint32_t lu = pk(a - blo(hu), c - bhi(hu));
            *(uint32_t*)(smb + W2TH_O + g * RS_W2 + hp * 4) = hu;
            *(uint32_t*)(smb + W2TL_O + g * RS_W2 + hp * 4) = lu;
        }
        if (t < 32)              ((float*)(smb + W3S_O))[t] = W3[t];
        if (t >= 32 && t < 64)   ((float*)(smb + B2S_O))[t - 32] = b2[t - 32];
    }
    __syncthreads();

    const int r0 = (lane >> 2);          // row-in-tile for accumulators
    const int cb = (lane & 3) * 2;       // col pair base

    // ================= Layer 1: h1 = relu(keys @ W1bot + qw) =================
    if (warp < 13) {
        const int m0 = warp * 16;
        float acc[8][4];
        #pragma unroll
        for (int n = 0; n < 8; ++n)
            #pragma unroll
            for (int j = 0; j < 4; ++j) acc[n][j] = 0.f;

        const int arow = m0 + (lane & 15);
        const uint32_t acolb = (lane >> 4) << 4;     // 0 or 16 bytes
        const uint32_t ah_base = sb + KHI_O + arow * RS_K + acolb;
        const uint32_t al_base = sb + KLO_O + arow * RS_K + acolb;
        const uint32_t bh_base = sb + W1TH_O + (lane >> 2) * RS_W1 + (lane & 3) * 4;
        const uint32_t bl_base = sb + W1TL_O + (lane >> 2) * RS_W1 + (lane & 3) * 4;

        #pragma unroll
        for (int k = 0; k < 8; ++k) {
            uint32_t ah[4], al[4];
            ldsm4(ah[0], ah[1], ah[2], ah[3], ah_base + k * 32);
            ldsm4(al[0], al[1], al[2], al[3], al_base + k * 32);
            #pragma unroll
            for (int n = 0; n < 8; ++n) {
                const uint32_t boff = n * 8 * RS_W1 + k * 32;
                const uint32_t bh0 = lds32(bh_base + boff);
                const uint32_t bh1 = lds32(bh_base + boff + 16);
                const uint32_t bl0 = lds32(bl_base + boff);
                const uint32_t bl1 = lds32(bl_base + boff + 16);
                mma_bf16(acc[n], ah, bh0, bh1);
                mma_bf16(acc[n], ah, bl0, bl1);
                mma_bf16(acc[n], al, bh0, bh1);
            }
        }

        // epilogue: + qw, relu, split to hi/lo bf16, store to h1
        const float* qwf = (const float*)(smb + QW_O);
        const int rA = m0 + r0, rB = rA + 8;
        #pragma unroll
        for (int n = 0; n < 8; ++n) {
            const int c = n * 8 + cb;
            const float qa = qwf[c], qb = qwf[c + 1];
            const float v0 = fmaxf(acc[n][0] + qa, 0.f);
            const float v1 = fmaxf(acc[n][1] + qb, 0.f);
            const float v2 = fmaxf(acc[n][2] + qa, 0.f);
            const float v3 = fmaxf(acc[n][3] + qb, 0.f);
            const uint32_t h01 = pk(v0, v1), h23 = pk(v2, v3);
            const uint32_t l01 = pk(v0 - blo(h01), v1 - bhi(h01));
            const uint32_t l23 = pk(v2 - blo(h23), v3 - bhi(h23));
            *(uint32_t*)(smb + H1HI_O + rA * RS_H1 + c * 2) = h01;
            *(uint32_t*)(smb + H1LO_O + rA * RS_H1 + c * 2) = l01;
            *(uint32_t*)(smb + H1HI_O + rB * RS_H1 + c * 2) = h23;
            *(uint32_t*)(smb + H1LO_O + rB * RS_H1 + c * 2) = l23;
        }
    }
    // CRITICAL: block barrier. h2 (layer-2 epilogue) aliases the W1T region,
    // so every warp must finish its layer-1 MMA reads of W1T before ANY warp
    // may write h2. (__syncwarp was a cross-warp race -> rel_err 1.89.)
    __syncthreads();

    // ================= Layer 2: h2 = relu(h1 @ W2 + b2) =================
    if (warp < 13) {
        const int m0 = warp * 16;
        float acc2[4][4];
        #pragma unroll
        for (int n = 0; n < 4; ++n)
            #pragma unroll
            for (int j = 0; j < 4; ++j) acc2[n][j] = 0.f;

        const int arow = m0 + (lane & 15);
        const uint32_t acolb = (lane >> 4) << 4;
        const uint32_t ah_base = sb + H1HI_O + arow * RS_H1 + acolb;
        const uint32_t al_base = sb + H1LO_O + arow * RS_H1 + acolb;
        const uint32_t bh_base = sb + W2TH_O + (lane >> 2) * RS_W2 + (lane & 3) * 4;
        const uint32_t bl_base = sb + W2TL_O + (lane >> 2) * RS_W2 + (lane & 3) * 4;

        #pragma unroll
        for (int k = 0; k < 4; ++k) {
            uint32_t ah[4], al[4];
            ldsm4(ah[0], ah[1], ah[2], ah[3], ah_base + k * 32);
            ldsm4(al[0], al[1], al[2], al[3], al_base + k * 32);
            #pragma unroll
            for (int n = 0; n < 4; ++n) {
                const uint32_t boff = n * 8 * RS_W2 + k * 32;
                const uint32_t bh0 = lds32(bh_base + boff);
                const uint32_t bh1 = lds32(bh_base + boff + 16);
                const uint32_t bl0 = lds32(bl_base + boff);
                const uint32_t bl1 = lds32(bl_base + boff + 16);
                mma_bf16(acc2[n], ah, bh0, bh1);
                mma_bf16(acc2[n], ah, bl0, bl1);
                mma_bf16(acc2[n], al, bh0, bh1);
            }
        }

        // epilogue: + b2, relu -> h2 fp32 (stride 33)
        const float* b2f = (const float*)(smb + B2S_O);
        float* h2 = (float*)(smb + H2_O);
        const int rA = m0 + r0, rB = rA + 8;
        #pragma unroll
        for (int n = 0; n < 4; ++n) {
            const int c = n * 8 + cb;
            const float ba = b2f[c], bb = b2f[c + 1];
            h2[rA * 33 + c]     = fmaxf(acc2[n][0] + ba, 0.f);
            h2[rA * 33 + c + 1] = fmaxf(acc2[n][1] + bb, 0.f);
            h2[rB * 33 + c]     = fmaxf(acc2[n][2] + ba, 0.f);
            h2[rB * 33 + c + 1] = fmaxf(acc2[n][3] + bb, 0.f);
        }
    }
    __syncthreads();

    // ================= Layer 3 + mask =================
    float* scf = (float*)(smb + SC_O);
    if (t < S_) {
        const float* h2r = (const float*)(smb + H2_O) + t * 33;
        const float* w3f = (const float*)(smb + W3S_O);
        float a0 = 0.f, a1 = 0.f;
        #pragma unroll
        for (int g = 0; g < G_; g += 2) {
            a0 = fmaf(h2r[g],     w3f[g],     a0);
            a1 = fmaf(h2r[g + 1], w3f[g + 1], a1);
        }
        float sc = a0 + a1 + b3[0];
        if (mask[(size_t)b * S_ + t] == 0) sc = -1e9f;
        scf[t] = sc;
    }
    __syncthreads();

    // ================= Softmax over S=200 =================
    float* redf = (float*)(smb + RED_O);
    float m = -3e38f;
    for (int s = t; s < S_; s += 512) m = fmaxf(m, scf[s]);
    #pragma unroll
    for (int o = 16; o; o >>= 1) m = fmaxf(m, __shfl_xor_sync(0xffffffffu, m, o));
    if (lane == 0) redf[warp] = m;
    __syncthreads();
    if (warp == 0) {
        float v = (lane < 16) ? redf[lane] : -3e38f;
        #pragma unroll
        for (int o = 16; o; o >>= 1) v = fmaxf(v, __shfl_xor_sync(0xffffffffu, v, o));
        if (lane == 0) redf[32] = v;
    }
    __syncthreads();
    const float bm = redf[32];

    float ps = 0.f;
    for (int s = t; s < S_; s += 512) {
        const float ex = expf(scf[s] - bm);
        scf[s] = ex;
        ps += ex;
    }
    #pragma unroll
    for (int o = 16; o; o >>= 1) ps += __shfl_xor_sync(0xffffffffu, ps, o);
    if (lane == 0) redf[warp] = ps;
    __syncthreads();
    if (warp == 0) {
        float v = (lane < 16) ? redf[lane] : 0.f;
        #pragma unroll
        for (int o = 16; o; o >>= 1) v += __shfl_xor_sync(0xffffffffu, v, o);
        if (lane == 0) redf[33] = v;
    }
    __syncthreads();
    const float inv = 1.0f / redf[33];

    float* out_w = out + (size_t)B_ * E_;
    for (int s = t; s < S_; s += 512) {
        const float w = scf[s] * inv;
        scf[s] = w;
        out_w[(size_t)b * S_ + s] = w;
    }
    __syncthreads();

    // ================= attended[e] = sum_s w[s] * keys[s][e] =================
    {
        const int p = t & 63;       // bf16 pair index over e (e = 2p, 2p+1)
        const int g = t >> 6;       // 8 groups of 25 s
        const char* hb = smb + KHI_O;
        const char* lb = smb + KLO_O;
        float a0 = 0.f, a1 = 0.f;
        const int sbeg = g * 25;
        #pragma unroll 5
        for (int s = sbeg; s < sbeg + 25; ++s) {
            const int off = s * RS_K + p * 4;
            const uint32_t hu = *(const uint32_t*)(hb + off);
            const uint32_t lu = *(const uint32_t*)(lb + off);
            const float w = scf[s];
            a0 = fmaf(w, blo(hu) + blo(lu), a0);
            a1 = fmaf(w, bhi(hu) + bhi(lu), a1);
        }
        float* apf = (float*)(smb + AP_O);
        apf[g * 128 + p * 2]     = a0;
        apf[g * 128 + p * 2 + 1] = a1;
    }
    __syncthreads();
    if (t < E_) {
        const float* apf = (const float*)(smb + AP_O);
        float a = 0.f;
        #pragma unroll
        for (int g = 0; g < 8; ++g) a += apf[g * 128 + t];
        out[(size_t)b * E_ + t] = a;
    }
}

extern "C" void kernel_launch(void* const* d_in, const int* in_sizes, int n_in,
                              void* d_out, int out_size) {
    const float* query = (const float*)d_in[0];
    const float* keys  = (const float*)d_in[1];
    const int*   mask  = (const int*)d_in[2];
    const float* W1    = (const float*)d_in[3];
    const float* b1    = (const float*)d_in[4];
    const float* W2    = (const float*)d_in[5];
    const float* b2    = (const float*)d_in[6];
    const float* W3    = (const float*)d_in[7];
    const float* b3    = (const float*)d_in[8];
    float* out = (float*)d_out;

    cudaFuncSetAttribute(attn_hmma_kernel,
                         cudaFuncAttributeMaxDynamicSharedMemorySize, SMEM_BYTES);
    attn_hmma_kernel<<<B_, 512, SMEM_BYTES>>>(query, keys, mask, W1, b1, W2, b2, W3, b3, out);
}

// round 6
// speedup vs baseline: 2.4123x; 1.6175x over previous
#include <cuda_runtime.h>
#include <cstdint>

#define B_ 4096
#define S_ 200
#define E_ 128
#define H_ 64
#define G_ 32

// ---- SMEM byte offsets ----------------------------------------------------
// KEYS: 200 rows x 512B. Staged fp32 (linear), converted IN PLACE to
//       hi bf16 [0,256) + lo bf16 [256,512) per row, XOR-swizzled (bits 4-6 ^ (row&7)<<4).
#define KEYS_O   0          // 102400
#define H1_O     102400     // 208 rows x 256B (hi [0,128) + lo [128,256), swizzled) = 53248
#define W1STG_O  102400     // 32KB fp32 staging (W1 top, then W1 bottom) - dead before H1 written
#define W2STG_O  135168     // 8KB fp32 W2 staging (inside H1 region)
#define W1T_O    155648     // 64 rows x 512B (hi [0,256) + lo [256,512), swizzled) = 32768
#define W2T_O    188416     // 32 rows x 256B (hi [0,128) + lo [128,256), swizzled) = 8192
#define H2_O     155648     // alias W1T after layer-1 (208*33*4 = 27456 < 32768)
#define AP_O     102400     // alias H1 after layer-2
#define QW_O     196608     // 64 f
#define QWP_O    196864     // 512 f (qw partials)
#define SC_O     198912     // 200 f
#define RED_O    199712     // 36 f
#define W3S_O    199856     // 32 f
#define B2S_O    199984     // 32 f
#define QS_O     200112     // 128 f (query row)
#define B1S_O    200624     // 64 f
#define MS_O     200880     // 200 i32 (mask row)
#define SMEM_BYTES 201696

// ---------------- helpers ----------------
static __device__ __forceinline__ uint32_t cvta_smem(const void* p) {
    uint32_t a;
    asm("{ .reg .u64 t; cvta.to.shared.u64 t, %1; cvt.u32.u64 %0, t; }" : "=r"(a) : "l"(p));
    return a;
}
static __device__ __forceinline__ uint32_t pk(float lo, float hi) { // lo->bits0-15, hi->bits16-31
    uint32_t r;
    asm("cvt.rn.bf16x2.f32 %0, %1, %2;" : "=r"(r) : "f"(hi), "f"(lo));
    return r;
}
static __device__ __forceinline__ float blo(uint32_t u) { return __uint_as_float(u << 16); }
static __device__ __forceinline__ float bhi(uint32_t u) { return __uint_as_float(u & 0xffff0000u); }

static __device__ __forceinline__ void ldsm4(uint32_t& r0, uint32_t& r1, uint32_t& r2, uint32_t& r3,
                                             uint32_t addr) {
    asm volatile("ldmatrix.sync.aligned.m8n8.x4.shared.b16 {%0,%1,%2,%3}, [%4];"
                 : "=r"(r0), "=r"(r1), "=r"(r2), "=r"(r3) : "r"(addr));
}
static __device__ __forceinline__ uint32_t lds32(uint32_t addr) {
    uint32_t v;
    asm volatile("ld.shared.u32 %0, [%1];" : "=r"(v) : "r"(addr));
    return v;
}
static __device__ __forceinline__ void mma_bf16(float* c, const uint32_t* a, uint32_t b0, uint32_t b1) {
    asm volatile("mma.sync.aligned.m16n8k16.row.col.f32.bf16.bf16.f32 "
                 "{%0,%1,%2,%3}, {%4,%5,%6,%7}, {%8,%9}, {%0,%1,%2,%3};"
                 : "+f"(c[0]), "+f"(c[1]), "+f"(c[2]), "+f"(c[3])
                 : "r"(a[0]), "r"(a[1]), "r"(a[2]), "r"(a[3]), "r"(b0), "r"(b1));
}

#define CPA(sm, g) asm volatile("cp.async.cg.shared.global [%0], [%1], 16;" :: "r"(sm), "l"(g))
#define CPC()      asm volatile("cp.async.commit_group;" ::: "memory")
#define CPW(n)     asm volatile("cp.async.wait_group %0;" :: "n"(n) : "memory")

__global__ __launch_bounds__(512, 1)
void attn_hmma_kernel(const float* __restrict__ query,
                      const float* __restrict__ keys,
                      const int*   __restrict__ mask,
                      const float* __restrict__ W1,
                      const float* __restrict__ b1,
                      const float* __restrict__ W2,
                      const float* __restrict__ b2,
                      const float* __restrict__ W3,
                      const float* __restrict__ b3,
                      float* __restrict__ out)
{
    extern __shared__ char smb[];
    const uint32_t sb = cvta_smem(smb);
    const int b    = blockIdx.x;
    const int t    = threadIdx.x;
    const int warp = t >> 5;
    const int lane = t & 31;

    // ================= Async fill: g0 = weights/q/mask, g1 = keys ==========
    {
        const char* gw1 = (const char*)W1;
        #pragma unroll
        for (int i = t; i < 2048; i += 512) CPA(sb + W1STG_O + i * 16, gw1 + i * 16);      // W1 top 32KB
        CPA(sb + W2STG_O + t * 16, (const char*)W2 + t * 16);                              // W2 8KB (512 thr)
        if (t < 32)  CPA(sb + QS_O  + t * 16, (const char*)(query + (size_t)b * E_) + t * 16);
        if (t < 16)  CPA(sb + B1S_O + t * 16, (const char*)b1 + t * 16);
        if (t < 8)   CPA(sb + B2S_O + t * 16, (const char*)b2 + t * 16);
        if (t < 8)   CPA(sb + W3S_O + t * 16, (const char*)W3 + t * 16);
        if (t < 50)  CPA(sb + MS_O  + t * 16, (const char*)(mask + (size_t)b * S_) + t * 16);
        CPC();   // group 0
        const char* gkb = (const char*)(keys) + (size_t)b * (S_ * E_ * 4);
        for (int i = t; i < 6400; i += 512) CPA(sb + KEYS_O + i * 16, gkb + (size_t)i * 16);
        CPC();   // group 1
    }
    CPW(1);              // g0 (weights etc.) complete
    __syncthreads();

    // ---- qw partials (all 512 threads) + W2T build ----
    {
        const int h  = t & 63;
        const int pp = t >> 6;                      // 0..7 split-K partial
        const float* stgt = (const float*)(smb + W1STG_O);
        const float* qs   = (const float*)(smb + QS_O);
        float s = (pp == 0) ? ((const float*)(smb + B1S_O))[h] : 0.f;
        #pragma unroll
        for (int j = 0; j < 16; ++j) {
            const int e = pp * 16 + j;
            s = fmaf(qs[e], stgt[e * 64 + h], s);
        }
        ((float*)(smb + QWP_O))[h * 8 + pp] = s;

        // W2T: [g][h] hi/lo bf16, swizzled
        const float* stg2 = (const float*)(smb + W2STG_O);
        {
            const int g  = t & 31;
            const int hp = t >> 5;                  // 0..15, need 0..31 -> 2 items
            #pragma unroll
            for (int r = 0; r < 2; ++r) {
                const int hq = hp + r * 16;         // h pair index 0..31
                const float a = stg2[(2 * hq) * G_ + g];
                const float c = stg2[(2 * hq + 1) * G_ + g];
                const uint32_t hu = pk(a, c);
                const uint32_t lu = pk(a - blo(hu), c - bhi(hu));
                char* dst = smb + W2T_O + g * 256 + (((uint32_t)(hq * 4)) ^ ((g & 7) << 4));
                *(uint32_t*)dst = hu;
                *(uint32_t*)(dst + 128) = lu;
            }
        }
    }
    __syncthreads();

    // ---- qw reduce + kick off W1 bottom (g2) ----
    if (t < 64) {
        const float* qp = (const float*)(smb + QWP_O) + t * 8;
        float s = 0.f;
        #pragma unroll
        for (int p = 0; p < 8; ++p) s += qp[p];
        ((float*)(smb + QW_O))[t] = s;
    }
    {
        const char* gw1b = (const char*)W1 + 32768;
        #pragma unroll
        for (int i = t; i < 2048; i += 512) CPA(sb + W1STG_O + i * 16, gw1b + i * 16);
        CPC();   // group 2
    }
    CPW(1);              // g1 (keys) complete (g2 may still fly)
    __syncthreads();

    // ---- Convert keys fp32 -> hi/lo bf16, IN PLACE, swizzled ----
    for (int r = warp; r < S_; r += 16) {
        const uint32_t rowb = (uint32_t)(r * 512);
        const float4 v = *(const float4*)(smb + rowb + lane * 16);
        const uint32_t h01 = pk(v.x, v.y), h23 = pk(v.z, v.w);
        const uint32_t l01 = pk(v.x - blo(h01), v.y - bhi(h01));
        const uint32_t l23 = pk(v.z - blo(h23), v.w - bhi(h23));
        const uint32_t xo = (uint32_t)((r & 7) << 4);
        *(uint64_t*)(smb + rowb + ((lane * 8) ^ xo))       = (uint64_t)h01 | ((uint64_t)h23 << 32);
        *(uint64_t*)(smb + rowb + 256 + ((lane * 8) ^ xo)) = (uint64_t)l01 | ((uint64_t)l23 << 32);
    }
    CPW(0);              // g2 (W1 bottom) complete
    __syncthreads();

    // ---- Build W1T [n][k] hi/lo bf16, swizzled ----
    {
        const float* stg = (const float*)(smb + W1STG_O);
        #pragma unroll
        for (int p = t; p < 4096; p += 512) {
            const int n  = p & 63;
            const int kp = p >> 6;                  // k-pair 0..63
            const float a = stg[(2 * kp) * H_ + n];
            const float c = stg[(2 * kp + 1) * H_ + n];
            const uint32_t hu = pk(a, c);
            const uint32_t lu = pk(a - blo(hu), c - bhi(hu));
            char* dst = smb + W1T_O + n * 512 + (((uint32_t)(kp * 4)) ^ ((n & 7) << 4));
            *(uint32_t*)dst = hu;
            *(uint32_t*)(dst + 256) = lu;
        }
    }
    __syncthreads();

    const int r0 = (lane >> 2);          // accumulator row-in-tile
    const int cb = (lane & 3) * 2;       // accumulator col pair base

    // ================= Layer 1: h1 = relu(keys @ W1bot + qw) =================
    if (warp < 13) {
        const int m0 = warp * 16;
        float acc[8][4];
        #pragma unroll
        for (int n = 0; n < 8; ++n)
            #pragma unroll
            for (int j = 0; j < 4; ++j) acc[n][j] = 0.f;

        const int arow = m0 + (lane & 15);
        const uint32_t axor = (uint32_t)((lane & 7) << 4);
        const uint32_t a_base = sb + KEYS_O + arow * 512;
        const uint32_t ag16 = (uint32_t)((lane >> 4) << 4);
        const uint32_t bxor = (uint32_t)((lane >> 2) << 4);
        const uint32_t bl4  = (uint32_t)((lane & 3) * 4);
        const uint32_t brow0 = sb + W1T_O + (lane >> 2) * 512;

        #pragma unroll
        for (int k = 0; k < 8; ++k) {
            uint32_t ah[4], al[4];
            const uint32_t ac = ((uint32_t)(k * 32) + ag16) ^ axor;
            ldsm4(ah[0], ah[1], ah[2], ah[3], a_base + ac);
            ldsm4(al[0], al[1], al[2], al[3], a_base + 256 + ac);
            const uint32_t c0 = ((uint32_t)(k * 32) ^ bxor) + bl4;
            const uint32_t c1 = ((uint32_t)(k * 32 + 16) ^ bxor) + bl4;
            #pragma unroll
            for (int n = 0; n < 8; ++n) {
                const uint32_t brow = brow0 + n * (8 * 512);
                const uint32_t bh0 = lds32(brow + c0);
                const uint32_t bh1 = lds32(brow + c1);
                const uint32_t bl0 = lds32(brow + 256 + c0);
                const uint32_t bl1 = lds32(brow + 256 + c1);
                mma_bf16(acc[n], ah, bh0, bh1);
                mma_bf16(acc[n], ah, bl0, bl1);
                mma_bf16(acc[n], al, bh0, bh1);
            }
        }

        // epilogue: + qw, relu, split hi/lo -> H1 (swizzled)
        const float* qwf = (const float*)(smb + QW_O);
        const int rA = m0 + r0, rB = rA + 8;
        const uint32_t exor = (uint32_t)((r0 & 7) << 4);
        #pragma unroll
        for (int n = 0; n < 8; ++n) {
            const int c = n * 8 + cb;
            const float qa = qwf[c], qb = qwf[c + 1];
            const float v0 = fmaxf(acc[n][0] + qa, 0.f);
            const float v1 = fmaxf(acc[n][1] + qb, 0.f);
            const float v2 = fmaxf(acc[n][2] + qa, 0.f);
            const float v3 = fmaxf(acc[n][3] + qb, 0.f);
            const uint32_t h01 = pk(v0, v1), h23 = pk(v2, v3);
            const uint32_t l01 = pk(v0 - blo(h01), v1 - bhi(h01));
            const uint32_t l23 = pk(v2 - blo(h23), v3 - bhi(h23));
            const uint32_t cB = (((uint32_t)(16 * n)) ^ exor) + (uint32_t)((lane & 3) * 4);
            *(uint32_t*)(smb + H1_O + rA * 256 + cB)       = h01;
            *(uint32_t*)(smb + H1_O + rA * 256 + 128 + cB) = l01;
            *(uint32_t*)(smb + H1_O + rB * 256 + cB)       = h23;
            *(uint32_t*)(smb + H1_O + rB * 256 + 128 + cB) = l23;
        }
    }
    // block barrier: all W1T reads done before any thread reuses that region,
    // and h1 visible to all warps.
    __syncthreads();

    // ================= Layer 2: h2 = relu(h1 @ W2 + b2) =================
    if (warp < 13) {
        const int m0 = warp * 16;
        float acc2[4][4];
        #pragma unroll
        for (int n = 0; n < 4; ++n)
            #pragma unroll
            for (int j = 0; j < 4; ++j) acc2[n][j] = 0.f;

        const int arow = m0 + (lane & 15);
        const uint32_t axor = (uint32_t)((lane & 7) << 4);
        const uint32_t a_base = sb + H1_O + arow * 256;
        const uint32_t ag16 = (uint32_t)((lane >> 4) << 4);
        const uint32_t bxor = (uint32_t)((lane >> 2) << 4);
        const uint32_t bl4  = (uint32_t)((lane & 3) * 4);
        const uint32_t brow0 = sb + W2T_O + (lane >> 2) * 256;

        #pragma unroll
        for (int k = 0; k < 4; ++k) {
            uint32_t ah[4], al[4];
            const uint32_t ac = ((uint32_t)(k * 32) + ag16) ^ axor;
            ldsm4(ah[0], ah[1], ah[2], ah[3], a_base + ac);
            ldsm4(al[0], al[1], al[2], al[3], a_base + 128 + ac);
            const uint32_t c0 = ((uint32_t)(k * 32) ^ bxor) + bl4;
            const uint32_t c1 = ((uint32_t)(k * 32 + 16) ^ bxor) + bl4;
            #pragma unroll
            for (int n = 0; n < 4; ++n) {
                const uint32_t brow = brow0 + n * (8 * 256);
                const uint32_t bh0 = lds32(brow + c0);
                const uint32_t bh1 = lds32(brow + c1);
                const uint32_t bl0 = lds32(brow + 128 + c0);
                const uint32_t bl1 = lds32(brow + 128 + c1);
                mma_bf16(acc2[n], ah, bh0, bh1);
                mma_bf16(acc2[n], ah, bl0, bl1);
                mma_bf16(acc2[n], al, bh0, bh1);
            }
        }

        // epilogue: + b2, relu -> h2 fp32 (stride 33)
        const float* b2f = (const float*)(smb + B2S_O);
        float* h2 = (float*)(smb + H2_O);
        const int rA = m0 + r0, rB = rA + 8;
        #pragma unroll
        for (int n = 0; n < 4; ++n) {
            const int c = n * 8 + cb;
            const float ba = b2f[c], bb = b2f[c + 1];
            h2[rA * 33 + c]     = fmaxf(acc2[n][0] + ba, 0.f);
            h2[rA * 33 + c + 1] = fmaxf(acc2[n][1] + bb, 0.f);
            h2[rB * 33 + c]     = fmaxf(acc2[n][2] + ba, 0.f);
            h2[rB * 33 + c + 1] = fmaxf(acc2[n][3] + bb, 0.f);
        }
    }
    __syncthreads();

    // ================= Layer 3 + mask =================
    float* scf = (float*)(smb + SC_O);
    if (t < S_) {
        const float* h2r = (const float*)(smb + H2_O) + t * 33;
        const float* w3f = (const float*)(smb + W3S_O);
        float a0 = 0.f, a1 = 0.f;
        #pragma unroll
        for (int g = 0; g < G_; g += 2) {
            a0 = fmaf(h2r[g],     w3f[g],     a0);
            a1 = fmaf(h2r[g + 1], w3f[g + 1], a1);
        }
        float sc = a0 + a1 + b3[0];
        if (((const int*)(smb + MS_O))[t] == 0) sc = -1e9f;
        scf[t] = sc;
    }
    __syncthreads();

    // ================= Softmax over S=200 =================
    float* redf = (float*)(smb + RED_O);
    float m = -3e38f;
    for (int s = t; s < S_; s += 512) m = fmaxf(m, scf[s]);
    #pragma unroll
    for (int o = 16; o; o >>= 1) m = fmaxf(m, __shfl_xor_sync(0xffffffffu, m, o));
    if (lane == 0) redf[warp] = m;
    __syncthreads();
    if (warp == 0) {
        float v = (lane < 16) ? redf[lane] : -3e38f;
        #pragma unroll
        for (int o = 16; o; o >>= 1) v = fmaxf(v, __shfl_xor_sync(0xffffffffu, v, o));
        if (lane == 0) redf[32] = v;
    }
    __syncthreads();
    const float bm = redf[32];

    float ps = 0.f;
    for (int s = t; s < S_; s += 512) {
        const float ex = expf(scf[s] - bm);
        scf[s] = ex;
        ps += ex;
    }
    #pragma unroll
    for (int o = 16; o; o >>= 1) ps += __shfl_xor_sync(0xffffffffu, ps, o);
    if (lane == 0) redf[warp] = ps;
    __syncthreads();
    if (warp == 0) {
        float v = (lane < 16) ? redf[lane] : 0.f;
        #pragma unroll
        for (int o = 16; o; o >>= 1) v += __shfl_xor_sync(0xffffffffu, v, o);
        if (lane == 0) redf[33] = v;
    }
    __syncthreads();
    const float inv = 1.0f / redf[33];

    float* out_w = out + (size_t)B_ * E_;
    for (int s = t; s < S_; s += 512) {
        const float w = scf[s] * inv;
        scf[s] = w;
        out_w[(size_t)b * S_ + s] = w;
    }
    __syncthreads();

    // ================= attended[e] = sum_s w[s] * keys[s][e] =================
    {
        const int p = t & 63;       // bf16 pair over e (e = 2p, 2p+1)
        const int g = t >> 6;       // 8 groups of 25 s
        float a0 = 0.f, a1 = 0.f;
        const int sbeg = g * 25;
        #pragma unroll 5
        for (int s = sbeg; s < sbeg + 25; ++s) {
            const uint32_t c = ((uint32_t)(4 * p)) ^ ((uint32_t)((s & 7) << 4));
            const uint32_t hu = *(const uint32_t*)(smb + s * 512 + c);
            const uint32_t lu = *(const uint32_t*)(smb + s * 512 + 256 + c);
            const float w = scf[s];
            a0 = fmaf(w, blo(hu) + blo(lu), a0);
            a1 = fmaf(w, bhi(hu) + bhi(lu), a1);
        }
        float* apf = (float*)(smb + AP_O);
        apf[g * 128 + p * 2]     = a0;
        apf[g * 128 + p * 2 + 1] = a1;
    }
    __syncthreads();
    if (t < E_) {
        const float* apf = (const float*)(smb + AP_O);
        float a = 0.f;
        #pragma unroll
        for (int g = 0; g < 8; ++g) a += apf[g * 128 + t];
        out[(size_t)b * E_ + t] = a;
    }
}

extern "C" void kernel_launch(void* const* d_in, const int* in_sizes, int n_in,
                              void* d_out, int out_size) {
    const float* query = (const float*)d_in[0];
    const float* keys  = (const float*)d_in[1];
    const int*   mask  = (const int*)d_in[2];
    const float* W1    = (const float*)d_in[3];
    const float* b1    = (const float*)d_in[4];
    const float* W2    = (const float*)d_in[5];
    const float* b2    = (const float*)d_in[6];
    const float* W3    = (const float*)d_in[7];
    const float* b3    = (const float*)d_in[8];
    float* out = (float*)d_out;

    cudaFuncSetAttribute(attn_hmma_kernel,
                         cudaFuncAttributeMaxDynamicSharedMemorySize, SMEM_BYTES);
    attn_hmma_kernel<<<B_, 512, SMEM_BYTES>>>(query, keys, mask, W1, b1, W2, b2, W3, b3, out);
}

// round 7
// speedup vs baseline: 2.6935x; 1.1166x over previous
#include <cuda_runtime.h>
#include <cstdint>

#define B_ 4096
#define S_ 200
#define E_ 128
#define H_ 64
#define G_ 32

// ---- SMEM layout (bytes) --------------------------------------------------
#define KEYS_O   0          // 200 rows x 512B: fp32 staged, converted in place to hi[0,256)+lo[256,512) bf16, xor-swizzled
#define W1T_O    102400     // 64 rows x 512B (hi 0-255 | lo 256-511), resident
#define W2T_O    135168     // 32 rows x 256B (hi 0-127 | lo 128-255), resident
#define QWALL_O  143360     // up to 40 iters x 64 f  (qw per assigned b)
#define SC_O     153600     // 200 f scores/weights
#define RED_O    154432     // reductions
#define W3S_O    154576     // 32 f
#define B2S_O    154704     // 32 f
#define B3S_O    154832     // 1 f (+pad)
#define MS0_O    154848     // mask slot 0 (200 i32)
#define MS1_O    155648     // mask slot 1
#define AP_O     156448     // 512 f attended partials
#define SMEM_BYTES 158720

// prologue staging (inside KEYS region, dead before first keys fetch)
#define PW1_O    0          // 65536B W1 fp32
#define PW2_O    65536      // 8192B  W2 fp32
#define PQ_O     73728      // nb x 512B q rows (nb<=37)
#define PB1_O    94208      // 256B b1

// ---------------- helpers ----------------
static __device__ __forceinline__ uint32_t cvta_smem(const void* p) {
    uint32_t a;
    asm("{ .reg .u64 t; cvta.to.shared.u64 t, %1; cvt.u32.u64 %0, t; }" : "=r"(a) : "l"(p));
    return a;
}
static __device__ __forceinline__ uint32_t pk(float lo, float hi) { // lo->bits0-15, hi->bits16-31
    uint32_t r;
    asm("cvt.rn.bf16x2.f32 %0, %1, %2;" : "=r"(r) : "f"(hi), "f"(lo));
    return r;
}
static __device__ __forceinline__ float blo(uint32_t u) { return __uint_as_float(u << 16); }
static __device__ __forceinline__ float bhi(uint32_t u) { return __uint_as_float(u & 0xffff0000u); }

static __device__ __forceinline__ void ldsm4(uint32_t& r0, uint32_t& r1, uint32_t& r2, uint32_t& r3,
                                             uint32_t addr) {
    asm volatile("ldmatrix.sync.aligned.m8n8.x4.shared.b16 {%0,%1,%2,%3}, [%4];"
                 : "=r"(r0), "=r"(r1), "=r"(r2), "=r"(r3) : "r"(addr));
}
static __device__ __forceinline__ uint32_t lds32(uint32_t addr) {
    uint32_t v;
    asm volatile("ld.shared.u32 %0, [%1];" : "=r"(v) : "r"(addr));
    return v;
}
static __device__ __forceinline__ void mma_bf16(float* c, const uint32_t* a, uint32_t b0, uint32_t b1) {
    asm volatile("mma.sync.aligned.m16n8k16.row.col.f32.bf16.bf16.f32 "
                 "{%0,%1,%2,%3}, {%4,%5,%6,%7}, {%8,%9}, {%0,%1,%2,%3};"
                 : "+f"(c[0]), "+f"(c[1]), "+f"(c[2]), "+f"(c[3])
                 : "r"(a[0]), "r"(a[1]), "r"(a[2]), "r"(a[3]), "r"(b0), "r"(b1));
}

#define CPA(sm, g) asm volatile("cp.async.cg.shared.global [%0], [%1], 16;" :: "r"(sm), "l"(g))
#define CPC()      asm volatile("cp.async.commit_group;" ::: "memory")
#define CPW(n)     asm volatile("cp.async.wait_group %0;" :: "n"(n) : "memory")

__global__ __launch_bounds__(512, 1)
void attn_persist_kernel(const float* __restrict__ query,
                         const float* __restrict__ keys,
                         const int*   __restrict__ mask,
                         const float* __restrict__ W1,
                         const float* __restrict__ b1,
                         const float* __restrict__ W2,
                         const float* __restrict__ b2,
                         const float* __restrict__ W3,
                         const float* __restrict__ b3,
                         float* __restrict__ out)
{
    extern __shared__ char smb[];
    const uint32_t sb = cvta_smem(smb);
    const int t    = threadIdx.x;
    const int warp = t >> 5;
    const int lane = t & 31;
    const int grid = gridDim.x;
    const int nb   = (B_ - blockIdx.x + grid - 1) / grid;   // iterations for this CTA

    // ================= Prologue: fetch all weights + my q rows ==============
    {
        #pragma unroll 4
        for (int i = t; i < 4096; i += 512) CPA(sb + PW1_O + i * 16, (const char*)W1 + i * 16);
        CPA(sb + PW2_O + t * 16, (const char*)W2 + t * 16);
        for (int j = t; j < nb * 32; j += 512) {
            const int bi = blockIdx.x + (j >> 5) * grid;
            CPA(sb + PQ_O + j * 16, (const char*)(query + (size_t)bi * E_) + (j & 31) * 16);
        }
        if (t < 16) CPA(sb + PB1_O + t * 16, (const char*)b1 + t * 16);
        if (t < 8)  CPA(sb + W3S_O + t * 16, (const char*)W3 + t * 16);
        if (t < 8)  CPA(sb + B2S_O + t * 16, (const char*)b2 + t * 16);
        CPC();
    }
    CPW(0);
    if (t == 0) ((float*)(smb + B3S_O))[0] = b3[0];
    __syncthreads();

    // ---- Build W1T (from W1 rows 128..255), hi/lo bf16, swizzled ----
    {
        const float* stg = (const float*)(smb + PW1_O + 32768);
        #pragma unroll
        for (int p = t; p < 4096; p += 512) {
            const int n  = p & 63;
            const int kp = p >> 6;
            const float a = stg[(2 * kp) * H_ + n];
            const float c = stg[(2 * kp + 1) * H_ + n];
            const uint32_t hu = pk(a, c);
            const uint32_t lu = pk(a - blo(hu), c - bhi(hu));
            char* dst = smb + W1T_O + n * 512 + (((uint32_t)(kp * 4)) ^ ((n & 7) << 4));
            *(uint32_t*)dst = hu;
            *(uint32_t*)(dst + 256) = lu;
        }
    }
    // ---- Build W2T, hi/lo bf16, swizzled ----
    {
        const float* stg2 = (const float*)(smb + PW2_O);
        #pragma unroll
        for (int p = t; p < 1024; p += 512) {
            const int g  = p & 31;
            const int hp = p >> 5;
            const float a = stg2[(2 * hp) * G_ + g];
            const float c = stg2[(2 * hp + 1) * G_ + g];
            const uint32_t hu = pk(a, c);
            const uint32_t lu = pk(a - blo(hu), c - bhi(hu));
            char* dst = smb + W2T_O + g * 256 + (((uint32_t)(hp * 4)) ^ ((g & 7) << 4));
            *(uint32_t*)dst = hu;
            *(uint32_t*)(dst + 128) = lu;
        }
    }
    // ---- qw[i][h] = b1[h] + q(b_i) @ W1_top, for all my iterations ----
    {
        const float* w1top = (const float*)(smb + PW1_O);
        const float* b1f   = (const float*)(smb + PB1_O);
        const int h    = t & 63;
        const int isub = t >> 6;                // 8 i's in parallel
        for (int i0 = 0; i0 < nb; i0 += 8) {
            const int i = i0 + isub;
            if (i < nb) {
                const float* q = (const float*)(smb + PQ_O) + i * 128;
                float s = b1f[h];
                #pragma unroll 8
                for (int e = 0; e < 128; ++e) s = fmaf(q[e], w1top[e * 64 + h], s);
                ((float*)(smb + QWALL_O))[i * 64 + h] = s;
            }
        }
    }
    __syncthreads();

    // ---- First keys + mask fetch ----
    {
        const int b0 = blockIdx.x;
        const char* gk = (const char*)keys + (size_t)b0 * (S_ * E_ * 4);
        for (int i = t; i < 6400; i += 512) CPA(sb + KEYS_O + i * 16, gk + (size_t)i * 16);
        if (t < 50) CPA(sb + MS0_O + t * 16, (const char*)(mask + (size_t)b0 * S_) + t * 16);
        CPC();
    }

    const int r0 = lane >> 2;
    const int cb = (lane & 3) * 2;

    // ================= Main loop over assigned b's ==========================
    for (int it = 0; it < nb; ++it) {
        const int b = blockIdx.x + it * grid;
        CPW(0);
        __syncthreads();

        // ---- Convert keys fp32 -> hi/lo bf16 in place, swizzled ----
        for (int r = warp; r < S_; r += 16) {
            const uint32_t rowb = (uint32_t)(r * 512);
            const float4 v = *(const float4*)(smb + rowb + lane * 16);
            const uint32_t h01 = pk(v.x, v.y), h23 = pk(v.z, v.w);
            const uint32_t l01 = pk(v.x - blo(h01), v.y - bhi(h01));
            const uint32_t l23 = pk(v.z - blo(h23), v.w - bhi(h23));
            const uint32_t xo = (uint32_t)((r & 7) << 4);
            *(uint64_t*)(smb + rowb + ((lane * 8) ^ xo))       = (uint64_t)h01 | ((uint64_t)h23 << 32);
            *(uint64_t*)(smb + rowb + 256 + ((lane * 8) ^ xo)) = (uint64_t)l01 | ((uint64_t)l23 << 32);
        }
        __syncthreads();

        uint32_t ahf[4][4], alf[4][4];          // h1 A-fragments (hi/lo), register-resident

        // ---- Layer 1: acc = keys @ W1bot (3-product split bf16) ----
        if (warp < 13) {
            const int m0 = warp * 16;
            float acc[8][4];
            #pragma unroll
            for (int n = 0; n < 8; ++n)
                #pragma unroll
                for (int j = 0; j < 4; ++j) acc[n][j] = 0.f;

            const int arow = m0 + (lane & 15);
            const uint32_t axor   = (uint32_t)((lane & 7) << 4);
            const uint32_t a_base = sb + KEYS_O + arow * 512;
            const uint32_t ag16   = (uint32_t)((lane >> 4) << 4);
            const uint32_t bxor   = (uint32_t)((lane >> 2) << 4);
            const uint32_t bl4    = (uint32_t)((lane & 3) * 4);
            const uint32_t brow0  = sb + W1T_O + (lane >> 2) * 512;

            #pragma unroll
            for (int k = 0; k < 8; ++k) {
                uint32_t ah[4], al[4];
                const uint32_t ac = ((uint32_t)(k * 32) + ag16) ^ axor;
                ldsm4(ah[0], ah[1], ah[2], ah[3], a_base + ac);
                ldsm4(al[0], al[1], al[2], al[3], a_base + 256 + ac);
                const uint32_t c0 = ((uint32_t)(k * 32) ^ bxor) + bl4;
                const uint32_t c1 = ((uint32_t)(k * 32 + 16) ^ bxor) + bl4;
                #pragma unroll
                for (int n = 0; n < 8; ++n) {
                    const uint32_t brow = brow0 + n * (8 * 512);
                    const uint32_t bh0 = lds32(brow + c0);
                    const uint32_t bh1 = lds32(brow + c1);
                    const uint32_t bl0 = lds32(brow + 256 + c0);
                    const uint32_t bl1 = lds32(brow + 256 + c1);
                    mma_bf16(acc[n], ah, bh0, bh1);
                    mma_bf16(acc[n], ah, bl0, bl1);
                    mma_bf16(acc[n], al, bh0, bh1);
                }
            }

            // epilogue: +qw, relu, split hi/lo -> A-fragments for layer 2.
            // C-frag of ctile n == A-frag slice: A ktile j <- ctiles 2j, 2j+1.
            const float* qwf = (const float*)(smb + QWALL_O) + it * 64;
            #pragma unroll
            for (int kt = 0; kt < 4; ++kt) {
                #pragma unroll
                for (int half = 0; half < 2; ++half) {
                    const int n = 2 * kt + half;
                    const int c = n * 8 + cb;
                    const float qa = qwf[c], qb = qwf[c + 1];
                    const float v0 = fmaxf(acc[n][0] + qa, 0.f);
                    const float v1 = fmaxf(acc[n][1] + qb, 0.f);
                    const float v2 = fmaxf(acc[n][2] + qa, 0.f);
                    const float v3 = fmaxf(acc[n][3] + qb, 0.f);
                    const uint32_t h01 = pk(v0, v1), h23 = pk(v2, v3);
                    ahf[kt][2 * half]     = h01;
                    ahf[kt][2 * half + 1] = h23;
                    alf[kt][2 * half]     = pk(v0 - blo(h01), v1 - bhi(h01));
                    alf[kt][2 * half + 1] = pk(v2 - blo(h23), v3 - bhi(h23));
                }
            }
        }
        __syncthreads();   // all keys SMEM reads done

        // ---- Prefetch keys(b+1) + mask into (now dead) keys buffer ----
        if (it + 1 < nb) {
            const int bn = b + grid;
            const char* gk = (const char*)keys + (size_t)bn * (S_ * E_ * 4);
            for (int i = t; i < 6400; i += 512) CPA(sb + KEYS_O + i * 16, gk + (size_t)i * 16);
            const uint32_t msn = ((it + 1) & 1) ? (sb + MS1_O) : (sb + MS0_O);
            if (t < 50) CPA(msn + t * 16, (const char*)(mask + (size_t)bn * S_) + t * 16);
            CPC();
        }

        // ---- Layer 2 (register A) + Layer 3 (register dot + shfl) ----
        float* scf = (float*)(smb + SC_O);
        if (warp < 13) {
            float acc2[4][4];
            #pragma unroll
            for (int n = 0; n < 4; ++n)
                #pragma unroll
                for (int j = 0; j < 4; ++j) acc2[n][j] = 0.f;

            const uint32_t bxor  = (uint32_t)((lane >> 2) << 4);
            const uint32_t bl4   = (uint32_t)((lane & 3) * 4);
            const uint32_t brow0 = sb + W2T_O + (lane >> 2) * 256;

            #pragma unroll
            for (int kt = 0; kt < 4; ++kt) {
                const uint32_t c0 = ((uint32_t)(kt * 32) ^ bxor) + bl4;
                const uint32_t c1 = ((uint32_t)(kt * 32 + 16) ^ bxor) + bl4;
                #pragma unroll
                for (int n = 0; n < 4; ++n) {
                    const uint32_t brow = brow0 + n * (8 * 256);
                    const uint32_t bh0 = lds32(brow + c0);
                    const uint32_t bh1 = lds32(brow + c1);
                    const uint32_t bl0 = lds32(brow + 128 + c0);
                    const uint32_t bl1 = lds32(brow + 128 + c1);
                    mma_bf16(acc2[n], ahf[kt], bh0, bh1);
                    mma_bf16(acc2[n], ahf[kt], bl0, bl1);
                    mma_bf16(acc2[n], alf[kt], bh0, bh1);
                }
            }

            // Layer 3 in registers: score = relu(acc2 + b2) . W3 + b3
            const float* b2f = (const float*)(smb + B2S_O);
            const float* w3f = (const float*)(smb + W3S_O);
            float p0 = 0.f, p8 = 0.f;
            #pragma unroll
            for (int n = 0; n < 4; ++n) {
                const int c = n * 8 + cb;
                const float w3a = w3f[c], w3b = w3f[c + 1];
                const float ba = b2f[c],  bb = b2f[c + 1];
                p0 = fmaf(fmaxf(acc2[n][0] + ba, 0.f), w3a,
                     fmaf(fmaxf(acc2[n][1] + bb, 0.f), w3b, p0));
                p8 = fmaf(fmaxf(acc2[n][2] + ba, 0.f), w3a,
                     fmaf(fmaxf(acc2[n][3] + bb, 0.f), w3b, p8));
            }
            p0 += __shfl_xor_sync(0xffffffffu, p0, 1);
            p0 += __shfl_xor_sync(0xffffffffu, p0, 2);
            p8 += __shfl_xor_sync(0xffffffffu, p8, 1);
            p8 += __shfl_xor_sync(0xffffffffu, p8, 2);
            if ((lane & 3) == 0) {
                const int rowA = warp * 16 + r0;
                const int rowB = rowA + 8;
                const float b3v = ((const float*)(smb + B3S_O))[0];
                const int* msk = (const int*)(smb + ((it & 1) ? MS1_O : MS0_O));
                if (rowA < S_) {
                    float sc = p0 + b3v;
                    if (msk[rowA] == 0) sc = -1e9f;
                    scf[rowA] = sc;
                }
                if (rowB < S_) {
                    float sc = p8 + b3v;
                    if (msk[rowB] == 0) sc = -1e9f;
                    scf[rowB] = sc;
                }
            }
        }
        __syncthreads();

        // ---- Softmax over S=200 ----
        float* redf = (float*)(smb + RED_O);
        float m = -3e38f;
        for (int s = t; s < S_; s += 512) m = fmaxf(m, scf[s]);
        #pragma unroll
        for (int o = 16; o; o >>= 1) m = fmaxf(m, __shfl_xor_sync(0xffffffffu, m, o));
        if (lane == 0) redf[warp] = m;
        __syncthreads();
        if (warp == 0) {
            float v = (lane < 16) ? redf[lane] : -3e38f;
            #pragma unroll
            for (int o = 16; o; o >>= 1) v = fmaxf(v, __shfl_xor_sync(0xffffffffu, v, o));
            if (lane == 0) redf[32] = v;
        }
        __syncthreads();
        const float bm = redf[32];

        float ps = 0.f;
        for (int s = t; s < S_; s += 512) {
            const float ex = expf(scf[s] - bm);
            scf[s] = ex;
            ps += ex;
        }
        #pragma unroll
        for (int o = 16; o; o >>= 1) ps += __shfl_xor_sync(0xffffffffu, ps, o);
        if (lane == 0) redf[warp] = ps;
        __syncthreads();
        if (warp == 0) {
            float v = (lane < 16) ? redf[lane] : 0.f;
            #pragma unroll
            for (int o = 16; o; o >>= 1) v += __shfl_xor_sync(0xffffffffu, v, o);
            if (lane == 0) redf[33] = v;
        }
        __syncthreads();
        const float inv = 1.0f / redf[33];

        float* out_w = out + (size_t)B_ * E_ + (size_t)b * S_;
        for (int s = t; s < S_; s += 512) {
            const float w = scf[s] * inv;
            scf[s] = w;
            out_w[s] = w;
        }
        __syncthreads();

        // ---- attended[e] = sum_s w[s]*keys[s][e], keys read from GLOBAL (L2-hot) ----
        {
            const int e  = t & 127;
            const int p4 = t >> 7;              // 4 partitions x 50 s
            const float* kg = keys + (size_t)b * (S_ * E_);
            float a = 0.f;
            const int sbeg = p4 * 50;
            #pragma unroll 5
            for (int s = sbeg; s < sbeg + 50; ++s)
                a = fmaf(scf[s], kg[s * E_ + e], a);
            ((float*)(smb + AP_O))[p4 * 128 + e] = a;
        }
        __syncthreads();
        if (t < E_) {
            const float* apf = (const float*)(smb + AP_O);
            out[(size_t)b * E_ + t] = apf[t] + apf[128 + t] + apf[256 + t] + apf[384 + t];
        }
        __syncthreads();
    }
}

extern "C" void kernel_launch(void* const* d_in, const int* in_sizes, int n_in,
                              void* d_out, int out_size) {
    const float* query = (const float*)d_in[0];
    const float* keys  = (const float*)d_in[1];
    const int*   mask  = (const int*)d_in[2];
    const float* W1    = (const float*)d_in[3];
    const float* b1    = (const float*)d_in[4];
    const float* W2    = (const float*)d_in[5];
    const float* b2    = (const float*)d_in[6];
    const float* W3    = (const float*)d_in[7];
    const float* b3    = (const float*)d_in[8];
    float* out = (float*)d_out;

    int nsm = 148;
    cudaDeviceGetAttribute(&nsm, cudaDevAttrMultiProcessorCount, 0);
    if (nsm < 112)  nsm = 112;    // keep nb <= 37 (QWALL sizing)
    if (nsm > 1024) nsm = 1024;

    cudaFuncSetAttribute(attn_persist_kernel,
                         cudaFuncAttributeMaxDynamicSharedMemorySize, SMEM_BYTES);
    attn_persist_kernel<<<nsm, 512, SMEM_BYTES>>>(query, keys, mask, W1, b1, W2, b2, W3, b3, out);
}